// round 16
// baseline (speedup 1.0000x reference)
#include <cuda_runtime.h>
#include <cuda_bf16.h>

#define NB 16
#define L 768
#define D 128
#define L3 256          // L / CLIP
#define KD 384          // CLIP * D
#define INV_T 0.08838834764831845f   // 1/sqrt(128)

__device__ float g_Lb[NB * L3 * L3 + 512];

typedef unsigned int u32;

// pre-split bf16 hi/lo planes of q, k, v
__device__ __nv_bfloat16 g_qh[NB * L * D], g_ql[NB * L * D];
__device__ __nv_bfloat16 g_kh[NB * L * D], g_kl[NB * L * D];
__device__ __nv_bfloat16 g_vh[NB * L * D], g_vl[NB * L * D];

// ---- bf16 split helpers --------------------------------------------------
__device__ __forceinline__ void split2(float x, float y, u32& hi, u32& lo) {
    __nv_bfloat16 hx = __float2bfloat16(x);
    __nv_bfloat16 hy = __float2bfloat16(y);
    __nv_bfloat16 lx = __float2bfloat16(x - __bfloat162float(hx));
    __nv_bfloat16 ly = __float2bfloat16(y - __bfloat162float(hy));
    __nv_bfloat162 h2 = __nv_bfloat162(hx, hy);
    __nv_bfloat162 l2 = __nv_bfloat162(lx, ly);
    hi = *(u32*)&h2;
    lo = *(u32*)&l2;
}

// ---- fast exp on fma/alu pipes (rel err ~3e-6) ---------------------------
__device__ __forceinline__ float fast_exp(float x) {
    float t = x * 1.4426950408889634f;
    float r = rintf(t);
    float f = t - r;
    float p = 1.3333558146428443e-3f;
    p = fmaf(p, f, 9.6181291076284772e-3f);
    p = fmaf(p, f, 5.5504108664821580e-2f);
    p = fmaf(p, f, 2.4022650695910072e-1f);
    p = fmaf(p, f, 6.9314718055994531e-1f);
    p = fmaf(p, f, 1.0f);
    return __int_as_float(__float_as_int(p) + ((int)r << 23));
}

// ---- ldmatrix / mma / cp.async ------------------------------------------
#define LDSM4(R0,R1,R2,R3,ADDR) \
    asm volatile("ldmatrix.sync.aligned.m8n8.x4.shared.b16 {%0,%1,%2,%3},[%4];" \
        : "=r"(R0),"=r"(R1),"=r"(R2),"=r"(R3) : "r"(ADDR))
#define LDSM2(R0,R1,ADDR) \
    asm volatile("ldmatrix.sync.aligned.m8n8.x2.shared.b16 {%0,%1},[%2];" \
        : "=r"(R0),"=r"(R1) : "r"(ADDR))
#define LDSM2T(R0,R1,ADDR) \
    asm volatile("ldmatrix.sync.aligned.m8n8.x2.trans.shared.b16 {%0,%1},[%2];" \
        : "=r"(R0),"=r"(R1) : "r"(ADDR))
#define MMAB(c, a, b0, b1) \
    asm("mma.sync.aligned.m16n8k16.row.col.f32.bf16.bf16.f32 " \
        "{%0,%1,%2,%3},{%4,%5,%6,%7},{%8,%9},{%0,%1,%2,%3};" \
        : "+f"(c[0]),"+f"(c[1]),"+f"(c[2]),"+f"(c[3]) \
        : "r"(a[0]),"r"(a[1]),"r"(a[2]),"r"(a[3]),"r"(b0),"r"(b1))
#define CPA(DST, SRC) \
    asm volatile("cp.async.cg.shared.global [%0],[%1],16;" :: "r"(DST), "l"(SRC))
#define CPC() asm volatile("cp.async.commit_group;")
#define CPW(N) asm volatile("cp.async.wait_group %0;" :: "n"(N))

// ---------------------------------------------------------------------------
// Kernel 0: split q/k/v into global bf16 hi/lo planes.
// ---------------------------------------------------------------------------
__global__ __launch_bounds__(256) void split_kernel(const float* __restrict__ q,
                                                    const float* __restrict__ k,
                                                    const float* __restrict__ v) {
    int t = blockIdx.x * 256 + threadIdx.x;   // over NB*L*D/4
    const float* s;
    __nv_bfloat16 *dh, *dl;
    if (blockIdx.y == 0)      { s = q; dh = g_qh; dl = g_ql; }
    else if (blockIdx.y == 1) { s = k; dh = g_kh; dl = g_kl; }
    else                      { s = v; dh = g_vh; dl = g_vl; }
    float4 x = *(const float4*)(s + (size_t)t * 4);
    u32 h0, l0, h1, l1;
    split2(x.x, x.y, h0, l0);
    split2(x.z, x.w, h1, l1);
    *(uint2*)(dh + (size_t)t * 4) = make_uint2(h0, h1);
    *(uint2*)(dl + (size_t)t * 4) = make_uint2(l0, l1);
}

// ---------------------------------------------------------------------------
// Kernel 1: local block GEMM with fc-weight folding fused into the A loader.
// ---------------------------------------------------------------------------
__global__ __launch_bounds__(256) void lb_kernel(const float* __restrict__ q,
                                                 const float* __restrict__ k,
                                                 const float* __restrict__ fc_w,
                                                 const float* __restrict__ fc_b) {
    __shared__ float sA[64][65];
    __shared__ float sB[64][65];
    const int b  = blockIdx.z;
    const int i0 = blockIdx.y * 64;
    const int j0 = blockIdx.x * 64;
    const int tid = threadIdx.x;
    const int txn = tid & 15;
    const int tym = tid >> 4;

    float w[9];
    #pragma unroll
    for (int x = 0; x < 9; ++x) w[x] = __ldg(fc_w + x);

    const float* qb = q + (size_t)b * L * D;
    const float* kb = k + (size_t)b * L * D;

    float acc[4][4] = {};

    for (int k0 = 0; k0 < KD; k0 += 64) {
        #pragma unroll
        for (int it = 0; it < 4; ++it) {
            int lin = tid + it * 256;
            int r  = lin >> 4;
            int c4 = lin & 15;
            int kcol = k0 + c4 * 4;
            int c = kcol >> 7;
            int d = kcol & 127;
            const float* qr = qb + (size_t)(3 * (i0 + r)) * D + d;
            float4 q0 = *(const float4*)qr;
            float4 q1 = *(const float4*)(qr + D);
            float4 q2 = *(const float4*)(qr + 2 * D);
            float w0 = w[c], w1 = w[3 + c], w2 = w[6 + c];
            sA[r][c4 * 4 + 0] = w0 * q0.x + w1 * q1.x + w2 * q2.x;
            sA[r][c4 * 4 + 1] = w0 * q0.y + w1 * q1.y + w2 * q2.y;
            sA[r][c4 * 4 + 2] = w0 * q0.z + w1 * q1.z + w2 * q2.z;
            sA[r][c4 * 4 + 3] = w0 * q0.w + w1 * q1.w + w2 * q2.w;
            float4 bv = *(const float4*)(kb + (size_t)(j0 + r) * KD + kcol);
            sB[r][c4 * 4 + 0] = bv.x; sB[r][c4 * 4 + 1] = bv.y;
            sB[r][c4 * 4 + 2] = bv.z; sB[r][c4 * 4 + 3] = bv.w;
        }
        __syncthreads();
        #pragma unroll 8
        for (int kk = 0; kk < 64; ++kk) {
            float a[4], bb[4];
            #pragma unroll
            for (int i = 0; i < 4; ++i) a[i]  = sA[tym * 4 + i][kk];
            #pragma unroll
            for (int j = 0; j < 4; ++j) bb[j] = sB[txn + 16 * j][kk];
            #pragma unroll
            for (int i = 0; i < 4; ++i)
                #pragma unroll
                for (int j = 0; j < 4; ++j) acc[i][j] += a[i] * bb[j];
        }
        __syncthreads();
    }

    const float bias = 128.0f * fc_b[0];
    float* Lbp = g_Lb + (size_t)b * L3 * L3;
    #pragma unroll
    for (int i = 0; i < 4; ++i)
        #pragma unroll
        for (int j = 0; j < 4; ++j)
            Lbp[(size_t)(i0 + tym * 4 + i) * L3 + (j0 + txn + 16 * j)] = acc[i][j] + bias;
}

// ---------------------------------------------------------------------------
// Kernel 2: fused attention, bf16 double-split + ldmatrix + cp.async pipeline.
// One CTA = (b, 32 q-rows), 256 threads (8 warps), chunk = 64, 12 chunks,
// 2 CTAs/SM. Pre-split planes loaded via cp.async.cg (L1 bypass) into
// SEPARATE K and V buffers: V(c) loads during phase1(c), K(c+1) during
// phase2(c) -> global latency off the critical path.
// SMEM: Qh/Ql 8704 ea | Kh/Kl 17408 ea | Vh/Vl 17408 ea | Eh/El 4608 ea |
//       RS 1024 = 97,280 B.
// ---------------------------------------------------------------------------
#define OFF_QH 0
#define OFF_QL 8704
#define OFF_KH 17408
#define OFF_KL 34816
#define OFF_VH 52224
#define OFF_VL 69632
#define OFF_EH 87040
#define OFF_EL 91648
#define OFF_RS 96256
#define SMEM_BYTES 97280

__global__ __launch_bounds__(256, 2) void fused_attn_kernel(
    const float* __restrict__ q, const float* __restrict__ k,
    const float* __restrict__ v, float* __restrict__ out,
    float* __restrict__ attn) {
    extern __shared__ __align__(16) char smem[];
    __nv_bfloat16* sEh = (__nv_bfloat16*)(smem + OFF_EH);
    __nv_bfloat16* sEl = (__nv_bfloat16*)(smem + OFF_EL);
    float* sRS = (float*)(smem + OFF_RS);
    const u32 sbase = (u32)__cvta_generic_to_shared(smem);

    const int b    = blockIdx.y;
    const int m0   = blockIdx.x * 32;
    const int tid  = threadIdx.x;
    const int lane = tid & 31;
    const int wid  = tid >> 5;      // 0..7
    const int gid  = lane >> 2;
    const int tig  = lane & 3;

    // ---- prologue: async-load Q planes (group 0) and K(0) (group 1) ----
    {
        #pragma unroll
        for (int it = 0; it < 2; ++it) {           // Q: 32 rows x 16 ops/plane
            int lin = tid + it * 256;
            int row = lin >> 4, c16 = lin & 15;
            size_t g = (size_t)((b * L + m0 + row) * D) + c16 * 8;
            CPA(sbase + OFF_QH + row * 272 + c16 * 16, g_qh + g);
            CPA(sbase + OFF_QL + row * 272 + c16 * 16, g_ql + g);
        }
        CPC();
        #pragma unroll
        for (int it = 0; it < 4; ++it) {           // K(0): 64 rows x 16 ops/plane
            int lin = tid + it * 256;
            int row = lin >> 4, c16 = lin & 15;
            size_t g = (size_t)((b * L + row) * D) + c16 * 8;
            CPA(sbase + OFF_KH + row * 272 + c16 * 16, g_kh + g);
            CPA(sbase + OFF_KL + row * 272 + c16 * 16, g_kl + g);
        }
        CPC();
    }

    const float* Lbp = g_Lb + (size_t)b * L3 * L3;
    int qi[4];
    #pragma unroll
    for (int r = 0; r < 4; ++r) qi[r] = (m0 + gid + 8 * r) / 3;

    // ldmatrix lane base addresses (bytes)
    const u32 aQ = sbase + OFF_QH + (lane & 15) * 272 + ((lane >> 4) << 4);
    const u32 aK = sbase + OFF_KH + (8 * wid + (lane & 7)) * 272 + ((lane & 8) ? 16 : 0);
    const u32 aE = sbase + OFF_EH + (lane & 15) * 144 + ((lane >> 4) << 4);
    const u32 aV = sbase + OFF_VH + (lane & 15) * 272 + 32 * wid;

    float O[2][2][4] = {};    // [mt][dt][reg]
    float rsum[4] = {};

    for (int c = 0; c < 12; ++c) {
        // ---- issue V(c) (overlaps phase1) ----
        #pragma unroll
        for (int it = 0; it < 4; ++it) {
            int lin = tid + it * 256;
            int row = lin >> 4, c16 = lin & 15;
            size_t g = (size_t)((b * L + c * 64 + row) * D) + c16 * 8;
            CPA(sbase + OFF_VH + row * 272 + c16 * 16, g_vh + g);
            CPA(sbase + OFF_VL + row * 272 + c16 * 16, g_vl + g);
        }
        CPC();

        CPW(1);            // K(c) (and Q on c=0) complete; V(c) may be in flight
        __syncthreads();

        // ---- S = Q @ K^T, 3-pass bf16 split (warp w: n in [8w,8w+8)) ----
        float C[2][4] = {};
        #pragma unroll
        for (int kt = 0; kt < 8; ++kt) {
            u32 bh[2], bl[2];
            LDSM2(bh[0], bh[1], aK + kt * 32);
            LDSM2(bl[0], bl[1], aK + 17408 + kt * 32);
            #pragma unroll
            for (int mt = 0; mt < 2; ++mt) {
                u32 ah[4], al[4];
                LDSM4(ah[0], ah[1], ah[2], ah[3], aQ + mt * 4352 + kt * 32);
                LDSM4(al[0], al[1], al[2], al[3], aQ + 8704 + mt * 4352 + kt * 32);
                MMAB(C[mt], ah, bh[0], bh[1]);
                MMAB(C[mt], ah, bl[0], bl[1]);
                MMAB(C[mt], al, bh[0], bh[1]);
            }
        }

        // ---- epilogue: e = exp((S+Lb)/T); split e; attn; rsum ----
        {
            int ncol = c * 64 + 8 * wid + 2 * tig;
            int kj0 = ncol / 3, kj1 = (ncol + 1) / 3;
            #pragma unroll
            for (int mt = 0; mt < 2; ++mt)
                #pragma unroll
                for (int h = 0; h < 2; ++h) {
                    int rp = 2 * mt + h;
                    int m  = gid + 8 * rp;
                    const float* lbr = Lbp + (size_t)qi[rp] * L3;
                    float e0 = fast_exp((C[mt][2 * h]     + __ldg(lbr + kj0)) * INV_T);
                    float e1 = fast_exp((C[mt][2 * h + 1] + __ldg(lbr + kj1)) * INV_T);
                    rsum[rp] += e0 + e1;
                    u32 ehi, elo;
                    split2(e0, e1, ehi, elo);
                    *(u32*)(sEh + m * 72 + 8 * wid + 2 * tig) = ehi;
                    *(u32*)(sEl + m * 72 + 8 * wid + 2 * tig) = elo;
                    *(float2*)(attn + (size_t)(b * L + m0 + m) * L + ncol) =
                        make_float2(e0, e1);
                }
        }
        __syncthreads();   // E visible; K buffer free

        // ---- issue K(c+1) (overlaps phase2), then wait V(c) ----
        if (c < 11) {
            #pragma unroll
            for (int it = 0; it < 4; ++it) {
                int lin = tid + it * 256;
                int row = lin >> 4, c16 = lin & 15;
                size_t g = (size_t)((b * L + (c + 1) * 64 + row) * D) + c16 * 8;
                CPA(sbase + OFF_KH + row * 272 + c16 * 16, g_kh + g);
                CPA(sbase + OFF_KL + row * 272 + c16 * 16, g_kl + g);
            }
            CPC();
            CPW(1);        // V(c) done; K(c+1) in flight
        } else {
            CPW(0);        // V(11) done
        }
        __syncthreads();

        // ---- O += E @ V, 3-pass bf16 split (warp w: d in [16w,16w+16)) ----
        #pragma unroll
        for (int kt2 = 0; kt2 < 4; ++kt2) {
            u32 ah0[4], al0[4], ah1[4], al1[4];
            LDSM4(ah0[0], ah0[1], ah0[2], ah0[3], aE + kt2 * 32);
            LDSM4(al0[0], al0[1], al0[2], al0[3], aE + 4608 + kt2 * 32);
            LDSM4(ah1[0], ah1[1], ah1[2], ah1[3], aE + 2304 + kt2 * 32);
            LDSM4(al1[0], al1[1], al1[2], al1[3], aE + 4608 + 2304 + kt2 * 32);
            #pragma unroll
            for (int dt = 0; dt < 2; ++dt) {
                u32 bh[2], bl[2];
                LDSM2T(bh[0], bh[1], aV + kt2 * 4352 + dt * 16);
                LDSM2T(bl[0], bl[1], aV + 17408 + kt2 * 4352 + dt * 16);
                MMAB(O[0][dt], ah0, bh[0], bh[1]);
                MMAB(O[0][dt], ah0, bl[0], bl[1]);
                MMAB(O[0][dt], al0, bh[0], bh[1]);
                MMAB(O[1][dt], ah1, bh[0], bh[1]);
                MMAB(O[1][dt], ah1, bl[0], bl[1]);
                MMAB(O[1][dt], al1, bh[0], bh[1]);
            }
        }
        __syncthreads();   // phase2 done -> V buffer free for next iter
    }

    // ---- cross-warp row sums ----
    #pragma unroll
    for (int rp = 0; rp < 4; ++rp) {
        float s = rsum[rp];
        s += __shfl_xor_sync(0xffffffffu, s, 1);
        s += __shfl_xor_sync(0xffffffffu, s, 2);
        if (tig == 0) sRS[(gid + 8 * rp) * 8 + wid] = s;
    }
    __syncthreads();
    float inv[4];
    #pragma unroll
    for (int rp = 0; rp < 4; ++rp) {
        const float* p = sRS + (gid + 8 * rp) * 8;
        inv[rp] = 1.0f / (p[0] + p[1] + p[2] + p[3] + p[4] + p[5] + p[6] + p[7]);
    }

    // ---- normalize attn in place (just-written -> L2 hits) ----
    #pragma unroll
    for (int rp = 0; rp < 4; ++rp) {
        float* arow = attn + (size_t)(b * L + m0 + gid + 8 * rp) * L;
        float iv = inv[rp];
        #pragma unroll
        for (int t = 0; t < 6; ++t) {
            float4* p = (float4*)arow + wid * 24 + tig * 6 + t;
            float4 vv = *p;
            vv.x *= iv; vv.y *= iv; vv.z *= iv; vv.w *= iv;
            *p = vv;
        }
    }

    // ---- normalized output ----
    #pragma unroll
    for (int mt = 0; mt < 2; ++mt)
        #pragma unroll
        for (int dt = 0; dt < 2; ++dt)
            #pragma unroll
            for (int h = 0; h < 2; ++h) {
                int rp = 2 * mt + h;
                int m  = gid + 8 * rp;
                float iv = inv[rp];
                float2 o = make_float2(O[mt][dt][2 * h] * iv, O[mt][dt][2 * h + 1] * iv);
                *(float2*)(out + (size_t)(b * L + m0 + m) * D + 16 * wid + 8 * dt + 2 * tig) = o;
            }
}

// ---------------------------------------------------------------------------
extern "C" void kernel_launch(void* const* d_in, const int* in_sizes, int n_in,
                              void* d_out, int out_size) {
    const float* q    = (const float*)d_in[0];
    const float* k    = (const float*)d_in[1];
    const float* v    = (const float*)d_in[2];
    const float* fc_w = (const float*)d_in[3];
    const float* fc_b = (const float*)d_in[4];

    float* out  = (float*)d_out;
    float* attn = out + (size_t)NB * L * D;

    split_kernel<<<dim3(NB * L * D / 4 / 256, 3), 256>>>(q, k, v);

    lb_kernel<<<dim3(4, 4, NB), 256>>>(q, k, fc_w, fc_b);

    cudaFuncSetAttribute(fused_attn_kernel,
                         cudaFuncAttributeMaxDynamicSharedMemorySize, SMEM_BYTES);
    fused_attn_kernel<<<dim3(24, NB), 256, SMEM_BYTES>>>(q, k, v, out, attn);
}